// round 7
// baseline (speedup 1.0000x reference)
#include <cuda_runtime.h>
#include <cuda_fp16.h>
#include <math.h>
#include <stdint.h>

// ---------------- problem sizes ----------------
#define NA 50000
#define NP 100000
#define HC 128
#define NH 8
#define EW 400000
#define ER 400000
#define EC 800000
#define EP (EW + EC)
#define BN_EPS 1e-5f

// ---------------- scratch layout (float units; KE/VE stored as half) -----
#define OFF_XA    0ull
#define OFF_XP    (OFF_XA   + (size_t)NA*128)
#define OFF_KQVA  (OFF_XP   + (size_t)NP*128)
#define OFF_KQVP  (OFF_KQVA + (size_t)NA*384)
#define OFF_KEP   (OFF_KQVP + (size_t)NP*384)        // half[(NA+NP)*128]
#define OFF_VEP   (OFF_KEP  + (size_t)(NA+NP)*64)
#define OFF_KEA   (OFF_VEP  + (size_t)(NA+NP)*64)    // half[NP*128]
#define OFF_VEA   (OFF_KEA  + (size_t)NP*64)
#define OFF_AGGA  (OFF_VEA  + (size_t)NP*64)
#define OFF_AGGP  (OFF_AGGA + (size_t)NA*128)
#define OFF_TMPA  (OFF_AGGP + (size_t)NP*128)
#define OFF_TMPP  (OFF_TMPA + (size_t)NA*128)
#define OFF_ALP   (OFF_TMPP + (size_t)NP*128)        // logits paper [EP*8]
#define OFF_ALA   (OFF_ALP  + (size_t)EP*8)          // logits author [ER*8]
#define OFF_STATS (OFF_ALA  + (size_t)ER*8)
// integer region
#define OFF_INT   (OFF_STATS + 512ull)
#define IOFF_ROWP 0ull
#define IOFF_ROWA (IOFF_ROWP + NP + 1)
#define IOFF_CURP (IOFF_ROWA + NA + 1)
#define IOFF_CURA (IOFF_CURP + NP)
#define IOFF_SRCP (IOFF_CURA + NA)
#define IOFF_SRCA (IOFF_SRCP + EP)
#define IOFF_DSTP (IOFF_SRCA + ER)
#define IOFF_DSTA (IOFF_DSTP + EP)
#define IOFF_BS   (IOFF_DSTA + ER)
#define INT_TOTAL (IOFF_BS + 256)
#define TOTAL_FLOATS (OFF_INT + INT_TOTAL + 64ull)

__device__ float g_scratch[TOTAL_FLOATS];

// ---------------- tf32 helpers ----------------
__device__ __forceinline__ uint32_t f2tf32(float x)
{
    uint32_t r;
    asm("cvt.rna.tf32.f32 %0, %1;" : "=r"(r) : "f"(x));
    return r;
}

__device__ __forceinline__ void mma_tf32(float4& c, const uint32_t* a, const uint32_t* b)
{
    asm volatile(
        "mma.sync.aligned.m16n8k8.row.col.f32.tf32.tf32.f32 "
        "{%0,%1,%2,%3}, {%4,%5,%6,%7}, {%8,%9}, {%0,%1,%2,%3};"
        : "+f"(c.x), "+f"(c.y), "+f"(c.z), "+f"(c.w)
        : "r"(a[0]), "r"(a[1]), "r"(a[2]), "r"(a[3]), "r"(b[0]), "r"(b[1]));
}

// ---------------- tf32x2 tensor-core GEMM (W split hi+lo; A single tf32) -------
__global__ void __launch_bounds__(256)
gemm_tf32(const float* __restrict__ A, const float* __restrict__ W,
          const float* __restrict__ bias, float* __restrict__ C,
          int M, int N, int K, int act,
          const float* __restrict__ xold, const float* __restrict__ skipv)
{
    __shared__ uint32_t As[128][20];
    __shared__ uint32_t Bs[16][136], Bl[16][136];

    const int bm = blockIdx.y * 128;
    const int bn = blockIdx.x * 128;
    const int tid = threadIdx.x;
    const int lane = tid & 31;
    const int warp = tid >> 5;
    const int wm = warp >> 2;
    const int wn = warp & 3;

    float4 acc[4][4];
#pragma unroll
    for (int i = 0; i < 4; i++)
#pragma unroll
        for (int j = 0; j < 4; j++) acc[i][j] = make_float4(0.f, 0.f, 0.f, 0.f);

    for (int k0 = 0; k0 < K; k0 += 16) {
#pragma unroll
        for (int i = 0; i < 2; i++) {
            int id  = tid + i * 256;
            int row = id >> 2;
            int kc  = (id & 3) * 4;
            int grow = bm + row;
            float4 v = make_float4(0.f, 0.f, 0.f, 0.f);
            if (grow < M) v = *(const float4*)(A + (size_t)grow * K + k0 + kc);
            As[row][kc + 0] = f2tf32(v.x); As[row][kc + 1] = f2tf32(v.y);
            As[row][kc + 2] = f2tf32(v.z); As[row][kc + 3] = f2tf32(v.w);
        }
#pragma unroll
        for (int i = 0; i < 2; i++) {
            int id  = tid + i * 256;
            int row = id >> 5;
            int col = (id & 31) * 4;
            float4 v = *(const float4*)(W + (size_t)(k0 + row) * N + bn + col);
            uint32_t h;
            h = f2tf32(v.x); Bs[row][col + 0] = h; Bl[row][col + 0] = f2tf32(v.x - __uint_as_float(h));
            h = f2tf32(v.y); Bs[row][col + 1] = h; Bl[row][col + 1] = f2tf32(v.y - __uint_as_float(h));
            h = f2tf32(v.z); Bs[row][col + 2] = h; Bl[row][col + 2] = f2tf32(v.z - __uint_as_float(h));
            h = f2tf32(v.w); Bs[row][col + 3] = h; Bl[row][col + 3] = f2tf32(v.w - __uint_as_float(h));
        }
        __syncthreads();

#pragma unroll
        for (int ks = 0; ks < 16; ks += 8) {
            uint32_t af[4][4];
            const int kc = ks + (lane & 3);
#pragma unroll
            for (int mf = 0; mf < 4; mf++) {
                int r = wm * 64 + mf * 16 + (lane >> 2);
                af[mf][0] = As[r][kc];
                af[mf][1] = As[r + 8][kc];
                af[mf][2] = As[r][kc + 4];
                af[mf][3] = As[r + 8][kc + 4];
            }
            uint32_t bh[4][2], bl[4][2];
#pragma unroll
            for (int nf = 0; nf < 4; nf++) {
                int n = wn * 32 + nf * 8 + (lane >> 2);
                bh[nf][0] = Bs[kc][n];     bl[nf][0] = Bl[kc][n];
                bh[nf][1] = Bs[kc + 4][n]; bl[nf][1] = Bl[kc + 4][n];
            }
#pragma unroll
            for (int mf = 0; mf < 4; mf++)
#pragma unroll
                for (int nf = 0; nf < 4; nf++) {
                    mma_tf32(acc[mf][nf], af[mf], bl[nf]);
                    mma_tf32(acc[mf][nf], af[mf], bh[nf]);
                }
        }
        __syncthreads();
    }

    const int lr = lane >> 2;
    const int lc = (lane & 3) * 2;
    float sk = 0.f;
    if (act == 2) sk = 1.f / (1.f + __expf(-skipv[0]));
    float2 bv[4];
#pragma unroll
    for (int nf = 0; nf < 4; nf++) {
        int c0 = bn + wn * 32 + nf * 8 + lc;
        bv[nf] = *(const float2*)(bias + c0);
    }
#pragma unroll
    for (int mf = 0; mf < 4; mf++) {
        int r0 = bm + wm * 64 + mf * 16 + lr;
        int r1 = r0 + 8;
#pragma unroll
        for (int nf = 0; nf < 4; nf++) {
            int c0 = bn + wn * 32 + nf * 8 + lc;
            float4 a = acc[mf][nf];
            float2 o0 = make_float2(a.x + bv[nf].x, a.y + bv[nf].y);
            float2 o1 = make_float2(a.z + bv[nf].x, a.w + bv[nf].y);
            if (act == 1) {
                o0.x = fmaxf(o0.x, 0.f); o0.y = fmaxf(o0.y, 0.f);
                o1.x = fmaxf(o1.x, 0.f); o1.y = fmaxf(o1.y, 0.f);
            } else if (act == 2) {
                if (r0 < M) {
                    float2 x0 = *(const float2*)(xold + (size_t)r0 * N + c0);
                    o0.x = sk * o0.x + (1.f - sk) * x0.x;
                    o0.y = sk * o0.y + (1.f - sk) * x0.y;
                }
                if (r1 < M) {
                    float2 x1 = *(const float2*)(xold + (size_t)r1 * N + c0);
                    o1.x = sk * o1.x + (1.f - sk) * x1.x;
                    o1.y = sk * o1.y + (1.f - sk) * x1.y;
                }
            }
            if (r0 < M) *(float2*)(C + (size_t)r0 * N + c0) = o0;
            if (r1 < M) *(float2*)(C + (size_t)r1 * N + c0) = o1;
        }
    }
}

// ------------- fused per-relation per-head K+V transform (writes half) -------------
__global__ void rel_transform_kv(const float* __restrict__ kqv,
                                 const float* __restrict__ Ak, const float* __restrict__ Av,
                                 __half* __restrict__ outK, __half* __restrict__ outV, int N)
{
    __shared__ float sAk[2048], sAv[2048];
    __shared__ float skk[128], svv[128];
    for (int i = threadIdx.x; i < 2048; i += 128) { sAk[i] = Ak[i]; sAv[i] = Av[i]; }
    __syncthreads();
    const int h = threadIdx.x >> 4;
    const int e = threadIdx.x & 15;
    for (int n = blockIdx.x; n < N; n += gridDim.x) {
        skk[threadIdx.x] = kqv[(size_t)n * 384 + threadIdx.x];
        svv[threadIdx.x] = kqv[(size_t)n * 384 + 256 + threadIdx.x];
        __syncthreads();
        float ak = 0.f, av = 0.f;
#pragma unroll
        for (int d = 0; d < 16; d++) {
            ak += skk[h * 16 + d] * sAk[(h * 16 + d) * 16 + e];
            av += svv[h * 16 + d] * sAv[(h * 16 + d) * 16 + e];
        }
        outK[(size_t)n * 128 + threadIdx.x] = __float2half(ak);
        outV[(size_t)n * 128 + threadIdx.x] = __float2half(av);
        __syncthreads();
    }
}

// ---------------- CSR build ----------------
__global__ void hist_kernel(const int* __restrict__ dst, int* __restrict__ deg, int E)
{
    int i = blockIdx.x * blockDim.x + threadIdx.x;
    if (i < E) atomicAdd(&deg[dst[i]], 1);
}

__global__ void scan_partial(const int* __restrict__ deg, int* __restrict__ row,
                             int* __restrict__ bsums, int n)
{
    __shared__ int warpsum[8];
    int t = threadIdx.x;
    int lane = t & 31, wid = t >> 5;
    int base = blockIdx.x * 1024 + t * 4;
    int v0 = (base + 0 < n) ? deg[base + 0] : 0;
    int v1 = (base + 1 < n) ? deg[base + 1] : 0;
    int v2 = (base + 2 < n) ? deg[base + 2] : 0;
    int v3 = (base + 3 < n) ? deg[base + 3] : 0;
    int e0 = 0, e1 = v0, e2 = e1 + v1, e3 = e2 + v2;
    int tot = e3 + v3;
    int inc = tot;
#pragma unroll
    for (int off = 1; off < 32; off <<= 1) {
        int y = __shfl_up_sync(0xffffffffu, inc, off);
        if (lane >= off) inc += y;
    }
    if (lane == 31) warpsum[wid] = inc;
    __syncthreads();
    if (wid == 0) {
        int w = (lane < 8) ? warpsum[lane] : 0;
#pragma unroll
        for (int off = 1; off < 8; off <<= 1) {
            int y = __shfl_up_sync(0xffffffffu, w, off);
            if (lane >= off) w += y;
        }
        if (lane < 8) warpsum[lane] = w;
    }
    __syncthreads();
    int warpExcl = (wid == 0) ? 0 : warpsum[wid - 1];
    int thrExcl = warpExcl + inc - tot;
    if (base + 0 < n) row[base + 0] = thrExcl + e0;
    if (base + 1 < n) row[base + 1] = thrExcl + e1;
    if (base + 2 < n) row[base + 2] = thrExcl + e2;
    if (base + 3 < n) row[base + 3] = thrExcl + e3;
    if (t == 0) bsums[blockIdx.x] = warpsum[7];
}

__global__ void scan_small(int* __restrict__ bsums, int nb)
{
    __shared__ int warpsum[8];
    int t = threadIdx.x;
    int lane = t & 31, wid = t >> 5;
    int v = (t < nb) ? bsums[t] : 0;
    int inc = v;
#pragma unroll
    for (int off = 1; off < 32; off <<= 1) {
        int y = __shfl_up_sync(0xffffffffu, inc, off);
        if (lane >= off) inc += y;
    }
    if (lane == 31) warpsum[wid] = inc;
    __syncthreads();
    if (wid == 0) {
        int w = (lane < 8) ? warpsum[lane] : 0;
#pragma unroll
        for (int off = 1; off < 8; off <<= 1) {
            int y = __shfl_up_sync(0xffffffffu, w, off);
            if (lane >= off) w += y;
        }
        if (lane < 8) warpsum[lane] = w;
    }
    __syncthreads();
    int warpExcl = (wid == 0) ? 0 : warpsum[wid - 1];
    int excl = warpExcl + inc - v;
    if (t < nb) bsums[t] = excl;
    if (t == 255) bsums[nb] = warpExcl + inc;
}

__global__ void add_off(int* __restrict__ row, int* __restrict__ cur,
                        const int* __restrict__ bsums, int n, int nb)
{
    int i = blockIdx.x * blockDim.x + threadIdx.x;
    if (i < n) {
        int r = row[i] + bsums[i >> 10];
        row[i] = r;
        cur[i] = r;
    }
    if (i == 0) row[n] = bsums[nb];
}

// scatter edge into CSR order; records src (+offset) and dst per slot
__global__ void scatter_kernel(const int* __restrict__ src, const int* __restrict__ dst,
                               int* __restrict__ cursor, int* __restrict__ outS,
                               int* __restrict__ outD, int E, int srcOffset)
{
    int i = blockIdx.x * blockDim.x + threadIdx.x;
    if (i >= E) return;
    int d = dst[i];
    int p = atomicAdd(&cursor[d], 1);
    outS[p] = src[i] + srcOffset;
    outD[p] = d;
}

// ---------------- pass 1: per-(slot,head) attention logits ----------------
// gid = slot*8 + h. dst sorted (CSR order) -> q loads cache-hot; 8 threads/edge
// read the 256B K row coalesced.
__global__ void alpha_csr(const float* __restrict__ kqv, const __half* __restrict__ KE,
                          const int* __restrict__ srccol, const int* __restrict__ dstcol,
                          const float* __restrict__ prelA, const float* __restrict__ prelB,
                          int relBoundary, float* __restrict__ alpha, int E)
{
    int gid = blockIdx.x * blockDim.x + threadIdx.x;
    if (gid >= E * NH) return;
    int e = gid >> 3, h = gid & 7;
    int s = srccol[e], d = dstcol[e];
    const float4* qp = (const float4*)(kqv + (size_t)d * 384 + 128 + h * 16);
    const __half2* kp = (const __half2*)(KE + (size_t)s * 128 + h * 16);
    float acc = 0.f;
#pragma unroll
    for (int i = 0; i < 4; i++) {
        float4 q = qp[i];
        float2 k0 = __half22float2(kp[i * 2]);
        float2 k1 = __half22float2(kp[i * 2 + 1]);
        acc += q.x * k0.x + q.y * k0.y + q.z * k1.x + q.w * k1.y;
    }
    float pr = (s >= relBoundary) ? prelB[h] : prelA[h];
    alpha[gid] = acc * pr * 0.25f;
}

// ---------------- pass 2: softmax + weighted V aggregate + gelu --------------
// warp per destination; 4-edge unrolled online softmax; no shfl in the loop.
__global__ void agg_csr(const float* __restrict__ alpha, const __half* __restrict__ VE,
                        const int* __restrict__ rowptr, const int* __restrict__ srccol,
                        float* __restrict__ agg, int N)
{
    int warp = (blockIdx.x * blockDim.x + threadIdx.x) >> 5;
    int lane = threadIdx.x & 31;
    if (warp >= N) return;
    int h = lane >> 2;
    int c = h * 16 + (lane & 3) * 4;
    int js = rowptr[warp], je = rowptr[warp + 1];
    float m = -INFINITY, s = 0.f;
    float4 acc = make_float4(0.f, 0.f, 0.f, 0.f);

    int j = js;
    for (; j + 3 < je; j += 4) {
        int s0 = srccol[j], s1 = srccol[j + 1], s2 = srccol[j + 2], s3 = srccol[j + 3];
        float a0 = alpha[(size_t)(j + 0) * 8 + h];
        float a1 = alpha[(size_t)(j + 1) * 8 + h];
        float a2 = alpha[(size_t)(j + 2) * 8 + h];
        float a3 = alpha[(size_t)(j + 3) * 8 + h];
        const __half2* vp0 = (const __half2*)(VE + (size_t)s0 * 128 + c);
        const __half2* vp1 = (const __half2*)(VE + (size_t)s1 * 128 + c);
        const __half2* vp2 = (const __half2*)(VE + (size_t)s2 * 128 + c);
        const __half2* vp3 = (const __half2*)(VE + (size_t)s3 * 128 + c);
        float2 v00 = __half22float2(vp0[0]), v01 = __half22float2(vp0[1]);
        float2 v10 = __half22float2(vp1[0]), v11 = __half22float2(vp1[1]);
        float2 v20 = __half22float2(vp2[0]), v21 = __half22float2(vp2[1]);
        float2 v30 = __half22float2(vp3[0]), v31 = __half22float2(vp3[1]);
        float gm = fmaxf(fmaxf(a0, a1), fmaxf(a2, a3));
        gm = fmaxf(gm, m);
        float scl = __expf(m - gm);
        float w0 = __expf(a0 - gm), w1 = __expf(a1 - gm);
        float w2 = __expf(a2 - gm), w3 = __expf(a3 - gm);
        s = s * scl + (w0 + w1) + (w2 + w3);
        acc.x = acc.x * scl + (w0 * v00.x + w1 * v10.x) + (w2 * v20.x + w3 * v30.x);
        acc.y = acc.y * scl + (w0 * v00.y + w1 * v10.y) + (w2 * v20.y + w3 * v30.y);
        acc.z = acc.z * scl + (w0 * v01.x + w1 * v11.x) + (w2 * v21.x + w3 * v31.x);
        acc.w = acc.w * scl + (w0 * v01.y + w1 * v11.y) + (w2 * v21.y + w3 * v31.y);
        m = gm;
    }
    for (; j < je; j++) {
        int sr = srccol[j];
        float a = alpha[(size_t)j * 8 + h];
        const __half2* vp = (const __half2*)(VE + (size_t)sr * 128 + c);
        float2 v0 = __half22float2(vp[0]), v1 = __half22float2(vp[1]);
        float gm = fmaxf(m, a);
        float scl = __expf(m - gm);
        float w = __expf(a - gm);
        s = s * scl + w;
        acc.x = acc.x * scl + w * v0.x;
        acc.y = acc.y * scl + w * v0.y;
        acc.z = acc.z * scl + w * v1.x;
        acc.w = acc.w * scl + w * v1.y;
        m = gm;
    }

    float inv = 1.f / (s + 1e-16f);
    float4 r;
    float v;
    v = acc.x * inv; r.x = 0.5f * v * (1.f + erff(v * 0.70710678118654752f));
    v = acc.y * inv; r.y = 0.5f * v * (1.f + erff(v * 0.70710678118654752f));
    v = acc.z * inv; r.z = 0.5f * v * (1.f + erff(v * 0.70710678118654752f));
    v = acc.w * inv; r.w = 0.5f * v * (1.f + erff(v * 0.70710678118654752f));
    *(float4*)(agg + (size_t)warp * 128 + c) = r;
}

// ---------------- BatchNorm ----------------
__global__ void bn_stats(const float* __restrict__ h, float* __restrict__ stats, int N)
{
    int c = threadIdx.x;
    int r0 = blockIdx.x * 256;
    int r1 = min(N, r0 + 256);
    float s = 0.f, s2 = 0.f;
    for (int r = r0; r < r1; r++) {
        float v = h[(size_t)r * 128 + c];
        s += v; s2 += v * v;
    }
    atomicAdd(&stats[c], s);
    atomicAdd(&stats[128 + c], s2);
}

__global__ void bn_apply(const float* __restrict__ h, const float* __restrict__ stats,
                         const float* __restrict__ gamma, const float* __restrict__ beta,
                         float* __restrict__ out, int N)
{
    int i = blockIdx.x * blockDim.x + threadIdx.x;
    if (i >= N * 128) return;
    int c = i & 127;
    float invN = 1.f / (float)N;
    float mu = stats[c] * invN;
    float var = stats[128 + c] * invN - mu * mu;
    float v = h[i];
    out[i] = (v - mu) * rsqrtf(var + BN_EPS) * gamma[c] + beta[c];
}

// ---------------------------------------------------------------
static inline int cdiv(long long a, long long b) { return (int)((a + b - 1) / b); }

extern "C" void kernel_launch(void* const* d_in, const int* in_sizes, int n_in,
                              void* d_out, int out_size)
{
    const float* x_author = (const float*)d_in[0];
    const float* x_paper  = (const float*)d_in[1];
    const int* writes_src = (const int*)d_in[2];
    const int* writes_dst = (const int*)d_in[3];
    const int* rev_src    = (const int*)d_in[4];
    const int* rev_dst    = (const int*)d_in[5];
    const int* cites_src  = (const int*)d_in[6];
    const int* cites_dst  = (const int*)d_in[7];
    const float* linA_W   = (const float*)d_in[8];
    const float* linA_b   = (const float*)d_in[9];
    const float* linP_W   = (const float*)d_in[10];
    const float* linP_b   = (const float*)d_in[11];
    const float* kqv_W    = (const float*)d_in[12];
    const float* kqv_b    = (const float*)d_in[13];
    const float* a_k      = (const float*)d_in[14];
    const float* a_v      = (const float*)d_in[15];
    const float* p_rel    = (const float*)d_in[16];
    const float* out_W    = (const float*)d_in[17];
    const float* out_b    = (const float*)d_in[18];
    const float* skipP    = (const float*)d_in[19];
    const float* bn_gamma = (const float*)d_in[20];
    const float* bn_beta  = (const float*)d_in[21];

    float* base = nullptr;
    cudaGetSymbolAddress((void**)&base, g_scratch);

    float* XA   = base + OFF_XA;
    float* XP   = base + OFF_XP;
    float* KQVA = base + OFF_KQVA;
    float* KQVP = base + OFF_KQVP;
    __half* KEP = (__half*)(base + OFF_KEP);
    __half* VEP = (__half*)(base + OFF_VEP);
    __half* KEA = (__half*)(base + OFF_KEA);
    __half* VEA = (__half*)(base + OFF_VEA);
    float* AGGA = base + OFF_AGGA;
    float* AGGP = base + OFF_AGGP;
    float* TMPA = base + OFF_TMPA;
    float* TMPP = base + OFF_TMPP;
    float* ALP  = base + OFF_ALP;
    float* ALA  = base + OFF_ALA;
    float* STA  = base + OFF_STATS;
    float* STP  = base + OFF_STATS + 256;
    int* ibase  = (int*)(base + OFF_INT);
    int* ROWP   = ibase + IOFF_ROWP;
    int* ROWA   = ibase + IOFF_ROWA;
    int* CURP   = ibase + IOFF_CURP;
    int* CURA   = ibase + IOFF_CURA;
    int* SRCP   = ibase + IOFF_SRCP;
    int* SRCA   = ibase + IOFF_SRCA;
    int* DSTP   = ibase + IOFF_DSTP;
    int* DSTA   = ibase + IOFF_DSTA;
    int* BS     = ibase + IOFF_BS;

    // -------- CSR build (once per launch) --------
    const int nbP = cdiv(NP, 1024), nbA = cdiv(NA, 1024);
    cudaMemsetAsync(CURP, 0, (size_t)NP * 4, 0);
    cudaMemsetAsync(CURA, 0, (size_t)NA * 4, 0);
    hist_kernel<<<cdiv(EW, 256), 256>>>(writes_dst, CURP, EW);
    hist_kernel<<<cdiv(EC, 256), 256>>>(cites_dst, CURP, EC);
    hist_kernel<<<cdiv(ER, 256), 256>>>(rev_dst, CURA, ER);
    scan_partial<<<nbP, 256>>>(CURP, ROWP, BS, NP);
    scan_small<<<1, 256>>>(BS, nbP);
    add_off<<<cdiv(NP, 256), 256>>>(ROWP, CURP, BS, NP, nbP);
    scan_partial<<<nbA, 256>>>(CURA, ROWA, BS, NA);
    scan_small<<<1, 256>>>(BS, nbA);
    add_off<<<cdiv(NA, 256), 256>>>(ROWA, CURA, BS, NA, nbA);
    scatter_kernel<<<cdiv(EW, 256), 256>>>(writes_src, writes_dst, CURP, SRCP, DSTP, EW, 0);
    scatter_kernel<<<cdiv(EC, 256), 256>>>(cites_src, cites_dst, CURP, SRCP, DSTP, EC, NA);
    scatter_kernel<<<cdiv(ER, 256), 256>>>(rev_src, rev_dst, CURA, SRCA, DSTA, ER, 0);

    // -------- input projections + relu --------
    gemm_tf32<<<dim3(1, cdiv(NA, 128)), 256>>>(x_author, linA_W, linA_b, XA, NA, 128, 128, 1, nullptr, nullptr);
    gemm_tf32<<<dim3(1, cdiv(NP, 128)), 256>>>(x_paper,  linP_W, linP_b, XP, NP, 128, 128, 1, nullptr, nullptr);

    for (int l = 0; l < 2; l++) {
        // KQV GEMMs
        gemm_tf32<<<dim3(3, cdiv(NA, 128)), 256>>>(XA, kqv_W + (size_t)(l * 2 + 0) * 128 * 384,
                                                   kqv_b + (size_t)(l * 2 + 0) * 384, KQVA, NA, 384, 128, 0, nullptr, nullptr);
        gemm_tf32<<<dim3(3, cdiv(NP, 128)), 256>>>(XP, kqv_W + (size_t)(l * 2 + 1) * 128 * 384,
                                                   kqv_b + (size_t)(l * 2 + 1) * 384, KQVP, NP, 384, 128, 0, nullptr, nullptr);

        // per-relation K/V transforms into combined half tables
        rel_transform_kv<<<2048, 128>>>(KQVA, a_k + (size_t)(l * 3 + 0) * 2048,
                                        a_v + (size_t)(l * 3 + 0) * 2048, KEP, VEP, NA);
        rel_transform_kv<<<2048, 128>>>(KQVP, a_k + (size_t)(l * 3 + 2) * 2048,
                                        a_v + (size_t)(l * 3 + 2) * 2048,
                                        KEP + (size_t)NA * 128, VEP + (size_t)NA * 128, NP);
        rel_transform_kv<<<2048, 128>>>(KQVP, a_k + (size_t)(l * 3 + 1) * 2048,
                                        a_v + (size_t)(l * 3 + 1) * 2048, KEA, VEA, NP);

        // pass 1: logits (edge-parallel)
        alpha_csr<<<cdiv((long long)EP * NH, 256), 256>>>(KQVP, KEP, SRCP, DSTP,
                                                          p_rel + (size_t)(l * 3 + 0) * NH,
                                                          p_rel + (size_t)(l * 3 + 2) * NH,
                                                          NA, ALP, EP);
        alpha_csr<<<cdiv((long long)ER * NH, 256), 256>>>(KQVA, KEA, SRCA, DSTA,
                                                          p_rel + (size_t)(l * 3 + 1) * NH,
                                                          p_rel + (size_t)(l * 3 + 1) * NH,
                                                          NP + 1, ALA, ER);

        // pass 2: softmax + aggregate + gelu
        agg_csr<<<cdiv((long long)NP * 32, 256), 256>>>(ALP, VEP, ROWP, SRCP, AGGP, NP);
        agg_csr<<<cdiv((long long)NA * 32, 256), 256>>>(ALA, VEA, ROWA, SRCA, AGGA, NA);

        // output projection + fused sigmoid-skip mix
        gemm_tf32<<<dim3(1, cdiv(NA, 128)), 256>>>(AGGA, out_W + (size_t)(l * 2 + 0) * 128 * 128,
                                                   out_b + (size_t)(l * 2 + 0) * 128, TMPA, NA, 128, 128, 2,
                                                   XA, skipP + (l * 2 + 0));
        gemm_tf32<<<dim3(1, cdiv(NP, 128)), 256>>>(AGGP, out_W + (size_t)(l * 2 + 1) * 128 * 128,
                                                   out_b + (size_t)(l * 2 + 1) * 128, TMPP, NP, 128, 128, 2,
                                                   XP, skipP + (l * 2 + 1));

        // batch norm (training-mode stats), per node type
        cudaMemsetAsync(STA, 0, 512 * 4, 0);
        bn_stats<<<cdiv(NA, 256), 128>>>(TMPA, STA, NA);
        bn_stats<<<cdiv(NP, 256), 128>>>(TMPP, STP, NP);
        float* outA = (l == 1) ? (float*)d_out : XA;
        float* outP = (l == 1) ? (float*)d_out + (size_t)NA * 128 : XP;
        bn_apply<<<cdiv((long long)NA * 128, 256), 256>>>(TMPA, STA, bn_gamma + (size_t)l * 128,
                                                          bn_beta + (size_t)l * 128, outA, NA);
        bn_apply<<<cdiv((long long)NP * 128, 256), 256>>>(TMPP, STP, bn_gamma + (size_t)l * 128,
                                                          bn_beta + (size_t)l * 128, outP, NP);
    }
}

// round 8
// speedup vs baseline: 1.4545x; 1.4545x over previous
#include <cuda_runtime.h>
#include <cuda_fp16.h>
#include <math.h>
#include <stdint.h>

// ---------------- problem sizes ----------------
#define NA 50000
#define NP 100000
#define HC 128
#define NH 8
#define EW 400000
#define ER 400000
#define EC 800000
#define EP (EW + EC)
#define BN_EPS 1e-5f

// ---------------- scratch layout (float units) ----------------
#define OFF_XA    0ull
#define OFF_XP    (OFF_XA   + (size_t)NA*128)
#define OFF_QA    (OFF_XP   + (size_t)NP*128)
#define OFF_QP    (OFF_QA   + (size_t)NA*128)
#define OFF_KVP   (OFF_QP   + (size_t)NP*128)        // half[(NA+NP)*256]
#define OFF_KVA   (OFF_KVP  + (size_t)(NA+NP)*128)   // half[NP*256]
#define OFF_AGGA  (OFF_KVA  + (size_t)NP*128)
#define OFF_AGGP  (OFF_AGGA + (size_t)NA*128)
#define OFF_TMPA  (OFF_AGGP + (size_t)NP*128)
#define OFF_TMPP  (OFF_TMPA + (size_t)NA*128)
#define OFF_WC    (OFF_TMPP + (size_t)NP*128)        // 6 * 128 * 256 composite KV weights
#define OFF_WCB   (OFF_WC   + 6ull*128*256)          // 6 * 256 composite biases
#define OFF_STATS (OFF_WCB  + 6ull*256)
// integer region
#define OFF_INT   (OFF_STATS + 512ull)
#define IOFF_ROWP 0ull
#define IOFF_ROWA (IOFF_ROWP + NP + 1)
#define IOFF_CURP (IOFF_ROWA + NA + 1)
#define IOFF_CURA (IOFF_CURP + NP)
#define IOFF_SRCP (IOFF_CURA + NA)
#define IOFF_SRCA (IOFF_SRCP + EP)
#define IOFF_BS   (IOFF_SRCA + ER)
#define INT_TOTAL (IOFF_BS + 256)
#define TOTAL_FLOATS (OFF_INT + INT_TOTAL + 64ull)

__device__ float g_scratch[TOTAL_FLOATS];

// ---------------- tf32 helpers ----------------
__device__ __forceinline__ uint32_t f2tf32(float x)
{
    uint32_t r;
    asm("cvt.rna.tf32.f32 %0, %1;" : "=r"(r) : "f"(x));
    return r;
}

__device__ __forceinline__ void mma_tf32(float4& c, const uint32_t* a, const uint32_t* b)
{
    asm volatile(
        "mma.sync.aligned.m16n8k8.row.col.f32.tf32.tf32.f32 "
        "{%0,%1,%2,%3}, {%4,%5,%6,%7}, {%8,%9}, {%0,%1,%2,%3};"
        : "+f"(c.x), "+f"(c.y), "+f"(c.z), "+f"(c.w)
        : "r"(a[0]), "r"(a[1]), "r"(a[2]), "r"(a[3]), "r"(b[0]), "r"(b[1]));
}

// ---------------- tf32x2 tensor-core GEMM (W split hi+lo; A single tf32) -------
// C[M, gridN] = A[M,K] @ W[K,*] + bias. BM=128, BN=128, BK=16, 8 warps 2x4.
// lda/ldw/ldc: row strides in elements. Ch != nullptr -> half output (C ignored).
// act: 0=none, 1=relu, 2=skip-mix
__global__ void __launch_bounds__(256)
gemm_tf32(const float* __restrict__ A, int lda, const float* __restrict__ W, int ldw,
          const float* __restrict__ bias, float* __restrict__ C, __half* __restrict__ Ch,
          int ldc, int M, int K, int act,
          const float* __restrict__ xold, const float* __restrict__ skipv)
{
    __shared__ uint32_t As[128][20];
    __shared__ uint32_t Bs[16][136], Bl[16][136];

    const int bm = blockIdx.y * 128;
    const int bn = blockIdx.x * 128;
    const int tid = threadIdx.x;
    const int lane = tid & 31;
    const int warp = tid >> 5;
    const int wm = warp >> 2;
    const int wn = warp & 3;

    float4 acc[4][4];
#pragma unroll
    for (int i = 0; i < 4; i++)
#pragma unroll
        for (int j = 0; j < 4; j++) acc[i][j] = make_float4(0.f, 0.f, 0.f, 0.f);

    for (int k0 = 0; k0 < K; k0 += 16) {
#pragma unroll
        for (int i = 0; i < 2; i++) {
            int id  = tid + i * 256;
            int row = id >> 2;
            int kc  = (id & 3) * 4;
            int grow = bm + row;
            float4 v = make_float4(0.f, 0.f, 0.f, 0.f);
            if (grow < M) v = *(const float4*)(A + (size_t)grow * lda + k0 + kc);
            As[row][kc + 0] = f2tf32(v.x); As[row][kc + 1] = f2tf32(v.y);
            As[row][kc + 2] = f2tf32(v.z); As[row][kc + 3] = f2tf32(v.w);
        }
#pragma unroll
        for (int i = 0; i < 2; i++) {
            int id  = tid + i * 256;
            int row = id >> 5;
            int col = (id & 31) * 4;
            float4 v = *(const float4*)(W + (size_t)(k0 + row) * ldw + bn + col);
            uint32_t h;
            h = f2tf32(v.x); Bs[row][col + 0] = h; Bl[row][col + 0] = f2tf32(v.x - __uint_as_float(h));
            h = f2tf32(v.y); Bs[row][col + 1] = h; Bl[row][col + 1] = f2tf32(v.y - __uint_as_float(h));
            h = f2tf32(v.z); Bs[row][col + 2] = h; Bl[row][col + 2] = f2tf32(v.z - __uint_as_float(h));
            h = f2tf32(v.w); Bs[row][col + 3] = h; Bl[row][col + 3] = f2tf32(v.w - __uint_as_float(h));
        }
        __syncthreads();

#pragma unroll
        for (int ks = 0; ks < 16; ks += 8) {
            uint32_t af[4][4];
            const int kc = ks + (lane & 3);
#pragma unroll
            for (int mf = 0; mf < 4; mf++) {
                int r = wm * 64 + mf * 16 + (lane >> 2);
                af[mf][0] = As[r][kc];
                af[mf][1] = As[r + 8][kc];
                af[mf][2] = As[r][kc + 4];
                af[mf][3] = As[r + 8][kc + 4];
            }
            uint32_t bh[4][2], bl[4][2];
#pragma unroll
            for (int nf = 0; nf < 4; nf++) {
                int n = wn * 32 + nf * 8 + (lane >> 2);
                bh[nf][0] = Bs[kc][n];     bl[nf][0] = Bl[kc][n];
                bh[nf][1] = Bs[kc + 4][n]; bl[nf][1] = Bl[kc + 4][n];
            }
#pragma unroll
            for (int mf = 0; mf < 4; mf++)
#pragma unroll
                for (int nf = 0; nf < 4; nf++) {
                    mma_tf32(acc[mf][nf], af[mf], bl[nf]);
                    mma_tf32(acc[mf][nf], af[mf], bh[nf]);
                }
        }
        __syncthreads();
    }

    const int lr = lane >> 2;
    const int lc = (lane & 3) * 2;
    float sk = 0.f;
    if (act == 2) sk = 1.f / (1.f + __expf(-skipv[0]));
    float2 bv[4];
#pragma unroll
    for (int nf = 0; nf < 4; nf++) {
        int c0 = bn + wn * 32 + nf * 8 + lc;
        bv[nf] = *(const float2*)(bias + c0);
    }
#pragma unroll
    for (int mf = 0; mf < 4; mf++) {
        int r0 = bm + wm * 64 + mf * 16 + lr;
        int r1 = r0 + 8;
#pragma unroll
        for (int nf = 0; nf < 4; nf++) {
            int c0 = bn + wn * 32 + nf * 8 + lc;
            float4 a = acc[mf][nf];
            float2 o0 = make_float2(a.x + bv[nf].x, a.y + bv[nf].y);
            float2 o1 = make_float2(a.z + bv[nf].x, a.w + bv[nf].y);
            if (act == 1) {
                o0.x = fmaxf(o0.x, 0.f); o0.y = fmaxf(o0.y, 0.f);
                o1.x = fmaxf(o1.x, 0.f); o1.y = fmaxf(o1.y, 0.f);
            } else if (act == 2) {
                if (r0 < M) {
                    float2 x0 = *(const float2*)(xold + (size_t)r0 * ldc + c0);
                    o0.x = sk * o0.x + (1.f - sk) * x0.x;
                    o0.y = sk * o0.y + (1.f - sk) * x0.y;
                }
                if (r1 < M) {
                    float2 x1 = *(const float2*)(xold + (size_t)r1 * ldc + c0);
                    o1.x = sk * o1.x + (1.f - sk) * x1.x;
                    o1.y = sk * o1.y + (1.f - sk) * x1.y;
                }
            }
            if (Ch) {
                if (r0 < M) *(__half2*)(Ch + (size_t)r0 * ldc + c0) = __floats2half2_rn(o0.x, o0.y);
                if (r1 < M) *(__half2*)(Ch + (size_t)r1 * ldc + c0) = __floats2half2_rn(o1.x, o1.y);
            } else {
                if (r0 < M) *(float2*)(C + (size_t)r0 * ldc + c0) = o0;
                if (r1 < M) *(float2*)(C + (size_t)r1 * ldc + c0) = o1;
            }
        }
    }
}

// ---------------- composite KV weights: WC[l,rel][r][c] ----------------
// c<128: K side: sum_d Wk[r, h*16+d] * Ak[h,d,e]; c>=128: V side.
__global__ void wcomp(const float* __restrict__ kqv_W, const float* __restrict__ a_k,
                      const float* __restrict__ a_v, float* __restrict__ WC)
{
    int gid = blockIdx.x * blockDim.x + threadIdx.x;
    if (gid >= 6 * 128 * 256) return;
    int lr = gid >> 15;
    int r  = (gid >> 8) & 127;
    int c  = gid & 255;
    int l = lr / 3, rel = lr % 3;
    int t = (rel == 0) ? 0 : 1;
    const float* Wb = kqv_W + (size_t)(l * 2 + t) * 128 * 384 + (size_t)r * 384 + ((c < 128) ? 0 : 256);
    int cc = c & 127;
    int h = cc >> 4, e = cc & 15;
    const float* Am = ((c < 128) ? a_k : a_v) + (size_t)(l * 3 + rel) * 2048 + h * 256 + e;
    float s = 0.f;
#pragma unroll
    for (int d = 0; d < 16; d++) s += Wb[h * 16 + d] * Am[d * 16];
    WC[gid] = s;
}

__global__ void bcomp(const float* __restrict__ kqv_b, const float* __restrict__ a_k,
                      const float* __restrict__ a_v, float* __restrict__ WCB)
{
    int gid = blockIdx.x * blockDim.x + threadIdx.x;
    if (gid >= 6 * 256) return;
    int lr = gid >> 8;
    int c  = gid & 255;
    int l = lr / 3, rel = lr % 3;
    int t = (rel == 0) ? 0 : 1;
    const float* bb = kqv_b + (size_t)(l * 2 + t) * 384 + ((c < 128) ? 0 : 256);
    int cc = c & 127;
    int h = cc >> 4, e = cc & 15;
    const float* Am = ((c < 128) ? a_k : a_v) + (size_t)(l * 3 + rel) * 2048 + h * 256 + e;
    float s = 0.f;
#pragma unroll
    for (int d = 0; d < 16; d++) s += bb[h * 16 + d] * Am[d * 16];
    WCB[gid] = s;
}

// ---------------- CSR build ----------------
__global__ void hist_kernel(const int* __restrict__ dst, int* __restrict__ deg, int E)
{
    int i = blockIdx.x * blockDim.x + threadIdx.x;
    if (i < E) atomicAdd(&deg[dst[i]], 1);
}

__global__ void scan_partial(const int* __restrict__ deg, int* __restrict__ row,
                             int* __restrict__ bsums, int n)
{
    __shared__ int warpsum[8];
    int t = threadIdx.x;
    int lane = t & 31, wid = t >> 5;
    int base = blockIdx.x * 1024 + t * 4;
    int v0 = (base + 0 < n) ? deg[base + 0] : 0;
    int v1 = (base + 1 < n) ? deg[base + 1] : 0;
    int v2 = (base + 2 < n) ? deg[base + 2] : 0;
    int v3 = (base + 3 < n) ? deg[base + 3] : 0;
    int e0 = 0, e1 = v0, e2 = e1 + v1, e3 = e2 + v2;
    int tot = e3 + v3;
    int inc = tot;
#pragma unroll
    for (int off = 1; off < 32; off <<= 1) {
        int y = __shfl_up_sync(0xffffffffu, inc, off);
        if (lane >= off) inc += y;
    }
    if (lane == 31) warpsum[wid] = inc;
    __syncthreads();
    if (wid == 0) {
        int w = (lane < 8) ? warpsum[lane] : 0;
#pragma unroll
        for (int off = 1; off < 8; off <<= 1) {
            int y = __shfl_up_sync(0xffffffffu, w, off);
            if (lane >= off) w += y;
        }
        if (lane < 8) warpsum[lane] = w;
    }
    __syncthreads();
    int warpExcl = (wid == 0) ? 0 : warpsum[wid - 1];
    int thrExcl = warpExcl + inc - tot;
    if (base + 0 < n) row[base + 0] = thrExcl + e0;
    if (base + 1 < n) row[base + 1] = thrExcl + e1;
    if (base + 2 < n) row[base + 2] = thrExcl + e2;
    if (base + 3 < n) row[base + 3] = thrExcl + e3;
    if (t == 0) bsums[blockIdx.x] = warpsum[7];
}

__global__ void scan_small(int* __restrict__ bsums, int nb)
{
    __shared__ int warpsum[8];
    int t = threadIdx.x;
    int lane = t & 31, wid = t >> 5;
    int v = (t < nb) ? bsums[t] : 0;
    int inc = v;
#pragma unroll
    for (int off = 1; off < 32; off <<= 1) {
        int y = __shfl_up_sync(0xffffffffu, inc, off);
        if (lane >= off) inc += y;
    }
    if (lane == 31) warpsum[wid] = inc;
    __syncthreads();
    if (wid == 0) {
        int w = (lane < 8) ? warpsum[lane] : 0;
#pragma unroll
        for (int off = 1; off < 8; off <<= 1) {
            int y = __shfl_up_sync(0xffffffffu, w, off);
            if (lane >= off) w += y;
        }
        if (lane < 8) warpsum[lane] = w;
    }
    __syncthreads();
    int warpExcl = (wid == 0) ? 0 : warpsum[wid - 1];
    int excl = warpExcl + inc - v;
    if (t < nb) bsums[t] = excl;
    if (t == 255) bsums[nb] = warpExcl + inc;
}

__global__ void add_off(int* __restrict__ row, int* __restrict__ cur,
                        const int* __restrict__ bsums, int n, int nb)
{
    int i = blockIdx.x * blockDim.x + threadIdx.x;
    if (i < n) {
        int r = row[i] + bsums[i >> 10];
        row[i] = r;
        cur[i] = r;
    }
    if (i == 0) row[n] = bsums[nb];
}

__global__ void scatter_kernel(const int* __restrict__ src, const int* __restrict__ dst,
                               int* __restrict__ cursor, int* __restrict__ out,
                               int E, int srcOffset)
{
    int i = blockIdx.x * blockDim.x + threadIdx.x;
    if (i >= E) return;
    int p = atomicAdd(&cursor[dst[i]], 1);
    out[p] = src[i] + srcOffset;
}

// ---------------- fused attention + softmax + aggregate + gelu (combined KV) ---------
// warp per destination; K and V for a source row are adjacent (256 halves/row).
__global__ void attn_agg(const float* __restrict__ Q, const __half* __restrict__ KV,
                         const int* __restrict__ rowptr, const int* __restrict__ srccol,
                         const float* __restrict__ prelA, const float* __restrict__ prelB,
                         int relBoundary, float* __restrict__ agg, int N)
{
    int warp = (blockIdx.x * blockDim.x + threadIdx.x) >> 5;
    int lane = threadIdx.x & 31;
    if (warp >= N) return;
    int h = lane >> 2;
    int c = h * 16 + (lane & 3) * 4;
    float4 q4 = *(const float4*)(Q + (size_t)warp * 128 + c);
    float pA = prelA[h] * 0.25f;
    float pB = prelB[h] * 0.25f;
    int js = rowptr[warp], je = rowptr[warp + 1];
    float m = -INFINITY, s = 0.f;
    float4 acc = make_float4(0.f, 0.f, 0.f, 0.f);

    int j = js;
    for (; j + 1 < je; j += 2) {
        int sr1 = srccol[j];
        int sr2 = srccol[j + 1];
        const __half2* kp1 = (const __half2*)(KV + (size_t)sr1 * 256 + c);
        const __half2* kp2 = (const __half2*)(KV + (size_t)sr2 * 256 + c);
        float2 k10 = __half22float2(kp1[0]), k11 = __half22float2(kp1[1]);
        float2 k20 = __half22float2(kp2[0]), k21 = __half22float2(kp2[1]);
        float p1 = q4.x * k10.x + q4.y * k10.y + q4.z * k11.x + q4.w * k11.y;
        float p2 = q4.x * k20.x + q4.y * k20.y + q4.z * k21.x + q4.w * k21.y;
        p1 += __shfl_xor_sync(0xffffffffu, p1, 1);
        p2 += __shfl_xor_sync(0xffffffffu, p2, 1);
        p1 += __shfl_xor_sync(0xffffffffu, p1, 2);
        p2 += __shfl_xor_sync(0xffffffffu, p2, 2);
        float a1 = p1 * ((sr1 >= relBoundary) ? pB : pA);
        float a2 = p2 * ((sr2 >= relBoundary) ? pB : pA);
        const __half2* vp1 = (const __half2*)(KV + (size_t)sr1 * 256 + 128 + c);
        const __half2* vp2 = (const __half2*)(KV + (size_t)sr2 * 256 + 128 + c);
        float2 v10 = __half22float2(vp1[0]), v11 = __half22float2(vp1[1]);
        float2 v20 = __half22float2(vp2[0]), v21 = __half22float2(vp2[1]);
        float newm = fmaxf(m, fmaxf(a1, a2));
        float scl = __expf(m - newm);
        float w1 = __expf(a1 - newm);
        float w2 = __expf(a2 - newm);
        s = s * scl + w1 + w2;
        acc.x = acc.x * scl + w1 * v10.x + w2 * v20.x;
        acc.y = acc.y * scl + w1 * v10.y + w2 * v20.y;
        acc.z = acc.z * scl + w1 * v11.x + w2 * v21.x;
        acc.w = acc.w * scl + w1 * v11.y + w2 * v21.y;
        m = newm;
    }
    for (; j < je; j++) {
        int sr = srccol[j];
        const __half2* kp = (const __half2*)(KV + (size_t)sr * 256 + c);
        float2 k0 = __half22float2(kp[0]), k1 = __half22float2(kp[1]);
        float part = q4.x * k0.x + q4.y * k0.y + q4.z * k1.x + q4.w * k1.y;
        part += __shfl_xor_sync(0xffffffffu, part, 1);
        part += __shfl_xor_sync(0xffffffffu, part, 2);
        float a = part * ((sr >= relBoundary) ? pB : pA);
        float newm = fmaxf(m, a);
        float scl = __expf(m - newm);
        float w = __expf(a - newm);
        s = s * scl + w;
        const __half2* vp = (const __half2*)(KV + (size_t)sr * 256 + 128 + c);
        float2 v0 = __half22float2(vp[0]), v1 = __half22float2(vp[1]);
        acc.x = acc.x * scl + w * v0.x;
        acc.y = acc.y * scl + w * v0.y;
        acc.z = acc.z * scl + w * v1.x;
        acc.w = acc.w * scl + w * v1.y;
        m = newm;
    }

    float inv = 1.f / (s + 1e-16f);
    float4 r;
    float v;
    v = acc.x * inv; r.x = 0.5f * v * (1.f + erff(v * 0.70710678118654752f));
    v = acc.y * inv; r.y = 0.5f * v * (1.f + erff(v * 0.70710678118654752f));
    v = acc.z * inv; r.z = 0.5f * v * (1.f + erff(v * 0.70710678118654752f));
    v = acc.w * inv; r.w = 0.5f * v * (1.f + erff(v * 0.70710678118654752f));
    *(float4*)(agg + (size_t)warp * 128 + c) = r;
}

// ---------------- BatchNorm ----------------
__global__ void bn_stats(const float* __restrict__ h, float* __restrict__ stats, int N)
{
    int c = threadIdx.x;
    int r0 = blockIdx.x * 256;
    int r1 = min(N, r0 + 256);
    float s = 0.f, s2 = 0.f;
    for (int r = r0; r < r1; r++) {
        float v = h[(size_t)r * 128 + c];
        s += v; s2 += v * v;
    }
    atomicAdd(&stats[c], s);
    atomicAdd(&stats[128 + c], s2);
}

__global__ void bn_apply(const float* __restrict__ h, const float* __restrict__ stats,
                         const float* __restrict__ gamma, const float* __restrict__ beta,
                         float* __restrict__ out, int N)
{
    int i = blockIdx.x * blockDim.x + threadIdx.x;
    if (i >= N * 128) return;
    int c = i & 127;
    float invN = 1.f / (float)N;
    float mu = stats[c] * invN;
    float var = stats[128 + c] * invN - mu * mu;
    float v = h[i];
    out[i] = (v - mu) * rsqrtf(var + BN_EPS) * gamma[c] + beta[c];
}

// ---------------------------------------------------------------
static inline int cdiv(long long a, long long b) { return (int)((a + b - 1) / b); }

extern "C" void kernel_launch(void* const* d_in, const int* in_sizes, int n_in,
                              void* d_out, int out_size)
{
    const float* x_author = (const float*)d_in[0];
    const float* x_paper  = (const float*)d_in[1];
    const int* writes_src = (const int*)d_in[2];
    const int* writes_dst = (const int*)d_in[3];
    const int* rev_src    = (const int*)d_in[4];
    const int* rev_dst    = (const int*)d_in[5];
    const int* cites_src  = (const int*)d_in[6];
    const int* cites_dst  = (const int*)d_in[7];
    const float* linA_W   = (const float*)d_in[8];
    const float* linA_b   = (const float*)d_in[9];
    const float* linP_W   = (const float*)d_in[10];
    const float* linP_b   = (const float*)d_in[11];
    const float* kqv_W    = (const float*)d_in[12];
    const float* kqv_b    = (const float*)d_in[13];
    const float* a_k      = (const float*)d_in[14];
    const float* a_v      = (const float*)d_in[15];
    const float* p_rel    = (const float*)d_in[16];
    const float* out_W    = (const float*)d_in[17];
    const float* out_b    = (const float*)d_in[18];
    const float* skipP    = (const float*)d_in[19];
    const float* bn_gamma = (const float*)d_in[20];
    const float* bn_beta  = (const float*)d_in[21];

    float* base = nullptr;
    cudaGetSymbolAddress((void**)&base, g_scratch);

    float* XA   = base + OFF_XA;
    float* XP   = base + OFF_XP;
    float* QA   = base + OFF_QA;
    float* QP   = base + OFF_QP;
    __half* KVP = (__half*)(base + OFF_KVP);
    __half* KVA = (__half*)(base + OFF_KVA);
    float* AGGA = base + OFF_AGGA;
    float* AGGP = base + OFF_AGGP;
    float* TMPA = base + OFF_TMPA;
    float* TMPP = base + OFF_TMPP;
    float* WC   = base + OFF_WC;
    float* WCB  = base + OFF_WCB;
    float* STA  = base + OFF_STATS;
    float* STP  = base + OFF_STATS + 256;
    int* ibase  = (int*)(base + OFF_INT);
    int* ROWP   = ibase + IOFF_ROWP;
    int* ROWA   = ibase + IOFF_ROWA;
    int* CURP   = ibase + IOFF_CURP;
    int* CURA   = ibase + IOFF_CURA;
    int* SRCP   = ibase + IOFF_SRCP;
    int* SRCA   = ibase + IOFF_SRCA;
    int* BS     = ibase + IOFF_BS;

    // -------- CSR build + composite weights (x-independent) --------
    const int nbP = cdiv(NP, 1024), nbA = cdiv(NA, 1024);
    cudaMemsetAsync(CURP, 0, (size_t)NP * 4, 0);
    cudaMemsetAsync(CURA, 0, (size_t)NA * 4, 0);
    hist_kernel<<<cdiv(EW, 256), 256>>>(writes_dst, CURP, EW);
    hist_kernel<<<cdiv(EC, 256), 256>>>(cites_dst, CURP, EC);
    hist_kernel<<<cdiv(ER, 256), 256>>>(rev_dst, CURA, ER);
    scan_partial<<<nbP, 256>>>(CURP, ROWP, BS, NP);
    scan_small<<<1, 256>>>(BS, nbP);
    add_off<<<cdiv(NP, 256), 256>>>(ROWP, CURP, BS, NP, nbP);
    scan_partial<<<nbA, 256>>>(CURA, ROWA, BS, NA);
    scan_small<<<1, 256>>>(BS, nbA);
    add_off<<<cdiv(NA, 256), 256>>>(ROWA, CURA, BS, NA, nbA);
    scatter_kernel<<<cdiv(EW, 256), 256>>>(writes_src, writes_dst, CURP, SRCP, EW, 0);
    scatter_kernel<<<cdiv(EC, 256), 256>>>(cites_src, cites_dst, CURP, SRCP, EC, NA);
    scatter_kernel<<<cdiv(ER, 256), 256>>>(rev_src, rev_dst, CURA, SRCA, ER, 0);
    wcomp<<<768, 256>>>(kqv_W, a_k, a_v, WC);
    bcomp<<<6, 256>>>(kqv_b, a_k, a_v, WCB);

    // -------- input projections + relu --------
    gemm_tf32<<<dim3(1, cdiv(NA, 128)), 256>>>(x_author, 128, linA_W, 128, linA_b,
                                               XA, nullptr, 128, NA, 128, 1, nullptr, nullptr);
    gemm_tf32<<<dim3(1, cdiv(NP, 128)), 256>>>(x_paper, 128, linP_W, 128, linP_b,
                                               XP, nullptr, 128, NP, 128, 1, nullptr, nullptr);

    for (int l = 0; l < 2; l++) {
        // Q projections (Q slice of kqv weights: cols [128,256))
        gemm_tf32<<<dim3(1, cdiv(NA, 128)), 256>>>(XA, 128, kqv_W + (size_t)(l * 2 + 0) * 128 * 384 + 128, 384,
                                                   kqv_b + (size_t)(l * 2 + 0) * 384 + 128,
                                                   QA, nullptr, 128, NA, 128, 0, nullptr, nullptr);
        gemm_tf32<<<dim3(1, cdiv(NP, 128)), 256>>>(XP, 128, kqv_W + (size_t)(l * 2 + 1) * 128 * 384 + 128, 384,
                                                   kqv_b + (size_t)(l * 2 + 1) * 384 + 128,
                                                   QP, nullptr, 128, NP, 128, 0, nullptr, nullptr);

        // combined K|V tables via composite weights, fp16 output
        // paper-destined: rel0 (author src) rows [0,NA), rel2 (paper src) rows [NA,NA+NP)
        gemm_tf32<<<dim3(2, cdiv(NA, 128)), 256>>>(XA, 128, WC + (size_t)(l * 3 + 0) * 128 * 256, 256,
                                                   WCB + (size_t)(l * 3 + 0) * 256,
                                                   nullptr, KVP, 256, NA, 128, 0, nullptr, nullptr);
        gemm_tf32<<<dim3(2, cdiv(NP, 128)), 256>>>(XP, 128, WC + (size_t)(l * 3 + 2) * 128 * 256, 256,
                                                   WCB + (size_t)(l * 3 + 2) * 256,
                                                   nullptr, KVP + (size_t)NA * 256, 256, NP, 128, 0, nullptr, nullptr);
        // author-destined: rel1 (paper src)
        gemm_tf32<<<dim3(2, cdiv(NP, 128)), 256>>>(XP, 128, WC + (size_t)(l * 3 + 1) * 128 * 256, 256,
                                                   WCB + (size_t)(l * 3 + 1) * 256,
                                                   nullptr, KVA, 256, NP, 128, 0, nullptr, nullptr);

        // fused attention + softmax + aggregation + gelu
        attn_agg<<<cdiv((long long)NP * 32, 256), 256>>>(QP, KVP, ROWP, SRCP,
                                                         p_rel + (size_t)(l * 3 + 0) * NH,
                                                         p_rel + (size_t)(l * 3 + 2) * NH,
                                                         NA, AGGP, NP);
        attn_agg<<<cdiv((long long)NA * 32, 256), 256>>>(QA, KVA, ROWA, SRCA,
                                                         p_rel + (size_t)(l * 3 + 1) * NH,
                                                         p_rel + (size_t)(l * 3 + 1) * NH,
                                                         NP + 1, AGGA, NA);

        // output projection + fused sigmoid-skip mix
        gemm_tf32<<<dim3(1, cdiv(NA, 128)), 256>>>(AGGA, 128, out_W + (size_t)(l * 2 + 0) * 128 * 128, 128,
                                                   out_b + (size_t)(l * 2 + 0) * 128,
                                                   TMPA, nullptr, 128, NA, 128, 2, XA, skipP + (l * 2 + 0));
        gemm_tf32<<<dim3(1, cdiv(NP, 128)), 256>>>(AGGP, 128, out_W + (size_t)(l * 2 + 1) * 128 * 128, 128,
                                                   out_b + (size_t)(l * 2 + 1) * 128,
                                                   TMPP, nullptr, 128, NP, 128, 2, XP, skipP + (l * 2 + 1));

        // batch norm (training-mode stats), per node type
        cudaMemsetAsync(STA, 0, 512 * 4, 0);
        bn_stats<<<cdiv(NA, 256), 128>>>(TMPA, STA, NA);
        bn_stats<<<cdiv(NP, 256), 128>>>(TMPP, STP, NP);
        float* outA = (l == 1) ? (float*)d_out : XA;
        float* outP = (l == 1) ? (float*)d_out + (size_t)NA * 128 : XP;
        bn_apply<<<cdiv((long long)NA * 128, 256), 256>>>(TMPA, STA, bn_gamma + (size_t)l * 128,
                                                          bn_beta + (size_t)l * 128, outA, NA);
        bn_apply<<<cdiv((long long)NP * 128, 256), 256>>>(TMPP, STP, bn_gamma + (size_t)l * 128,
                                                          bn_beta + (size_t)l * 128, outP, NP);
    }
}